// round 4
// baseline (speedup 1.0000x reference)
#include <cuda_runtime.h>
#include <cstdint>
#include <cstdio>

#define Bb 2
#define Tt 2048
#define Dd 1024
#define Hh 16
#define HDIM 64
#define MM (Bb*Tt)   // 4096

// ---------------- scratch (static device allocations are allowed) ----------
__device__ float g_xw[Bb*Tt*Dd];
__device__ float g_xr[Bb*Tt*Dd];
__device__ float g_xk[Bb*Tt*Dd];
__device__ float g_xv[Bb*Tt*Dd];
__device__ float g_xg[Bb*Tt*Dd];
__device__ float g_r [Bb*Tt*Dd];
__device__ float g_k [Bb*Tt*Dd];
__device__ float g_v [Bb*Tt*Dd];
__device__ float g_g [Bb*Tt*Dd];
__device__ float g_w [Bb*Tt*Dd];
__device__ float g_h [MM*64];
__device__ float g_y [Bb*Tt*Dd];
__device__ float g_yg[Bb*Tt*Dd];

// ---------------- small PTX helpers ---------------------------------------
__device__ __forceinline__ uint32_t smem_u32(const void* p){
    return (uint32_t)__cvta_generic_to_shared(p);
}
__device__ __forceinline__ void cp16(uint32_t s, const void* g){
    asm volatile("cp.async.cg.shared.global [%0], [%1], 16;\n" :: "r"(s), "l"(g));
}
__device__ __forceinline__ void cp4(uint32_t s, const void* g){
    asm volatile("cp.async.ca.shared.global [%0], [%1], 4;\n" :: "r"(s), "l"(g));
}
__device__ __forceinline__ void cp_commit(){
    asm volatile("cp.async.commit_group;\n");
}
template<int N> __device__ __forceinline__ void cp_wait(){
    asm volatile("cp.async.wait_group %0;\n" :: "n"(N));
}
__device__ __forceinline__ void mma_tf32(float c[4], const uint32_t a[4], const uint32_t b[2]){
    asm volatile(
        "mma.sync.aligned.m16n8k8.row.col.f32.tf32.tf32.f32 "
        "{%0,%1,%2,%3}, {%4,%5,%6,%7}, {%8,%9}, {%0,%1,%2,%3};\n"
        : "+f"(c[0]), "+f"(c[1]), "+f"(c[2]), "+f"(c[3])
        : "r"(a[0]), "r"(a[1]), "r"(a[2]), "r"(a[3]), "r"(b[0]), "r"(b[1]));
}
__device__ __forceinline__ uint32_t f2tf32(float x){
    uint32_t r;
    asm("cvt.rna.tf32.f32 %0, %1;\n" : "=r"(r) : "f"(x));
    return r;
}
__device__ __forceinline__ void split_tf32(float x, uint32_t& hi, uint32_t& lo){
    hi = f2tf32(x);
    lo = f2tf32(x - __uint_as_float(hi));
}

// ---------------- prep: token-shift interpolation --------------------------
__global__ __launch_bounds__(256) void prep_kernel(
    const float* __restrict__ x,
    const float* __restrict__ mw, const float* __restrict__ mr,
    const float* __restrict__ mk, const float* __restrict__ mv,
    const float* __restrict__ mg)
{
    size_t i4 = (size_t)blockIdx.x * 256 + threadIdx.x;   // over B*T*D/4
    size_t idx = i4 * 4;
    if (idx >= (size_t)Bb*Tt*Dd) return;
    int d = (int)(idx & (Dd-1));
    int t = (int)((idx >> 10) & (Tt-1));
    float4 xc = *(const float4*)(x + idx);
    float4 xs = make_float4(0.f,0.f,0.f,0.f);
    if (t > 0) xs = *(const float4*)(x + idx - Dd);
    float xx0 = xs.x - xc.x, xx1 = xs.y - xc.y, xx2 = xs.z - xc.z, xx3 = xs.w - xc.w;

    float4 m;
    m = *(const float4*)(mw + d);
    *(float4*)(g_xw + idx) = make_float4(xc.x + xx0*m.x, xc.y + xx1*m.y, xc.z + xx2*m.z, xc.w + xx3*m.w);
    m = *(const float4*)(mr + d);
    *(float4*)(g_xr + idx) = make_float4(xc.x + xx0*m.x, xc.y + xx1*m.y, xc.z + xx2*m.z, xc.w + xx3*m.w);
    m = *(const float4*)(mk + d);
    *(float4*)(g_xk + idx) = make_float4(xc.x + xx0*m.x, xc.y + xx1*m.y, xc.z + xx2*m.z, xc.w + xx3*m.w);
    m = *(const float4*)(mv + d);
    *(float4*)(g_xv + idx) = make_float4(xc.x + xx0*m.x, xc.y + xx1*m.y, xc.z + xx2*m.z, xc.w + xx3*m.w);
    m = *(const float4*)(mg + d);
    *(float4*)(g_xg + idx) = make_float4(xc.x + xx0*m.x, xc.y + xx1*m.y, xc.z + xx2*m.z, xc.w + xx3*m.w);
}

// ---------------- 3xTF32 GEMM: C[M,N] = A[M,K] @ B[K,N] --------------------
// Epilogues: 0 none, 1 silu, 2 tanh, 3 wdec = exp(-exp(w0[n]+v))
template<int EPI> __device__ __forceinline__ float epi_f(float v, float w0v){
    if (EPI == 1) return v / (1.f + expf(-v));
    if (EPI == 2) return tanhf(v);
    if (EPI == 3) return expf(-expf(w0v + v));
    return v;
}

template<int BN, int EPI>
__global__ __launch_bounds__(256) void gemm_tf32(
    const float* __restrict__ A, const float* __restrict__ B,
    float* __restrict__ C, int M, int N, int K,
    const float* __restrict__ w0)
{
    constexpr int BM = 128, BK = 16;
    constexpr int AST = BK + 4;       // 20 words: conflict-free fragment loads
    constexpr int BST = BN + 8;       // conflict-free fragment loads
    constexpr int WN  = BN / 2;
    constexpr int NT  = WN / 8;
    __shared__ __align__(16) float As[2][BM*AST];
    __shared__ __align__(16) float Bs[2][BK*BST];

    const int tid  = threadIdx.x;
    const int warp = tid >> 5, lane = tid & 31;
    const int wm = warp & 3, wn = warp >> 2;   // 4 x 2 warp grid
    const int grp = lane >> 2, qd = lane & 3;
    const int bm0 = blockIdx.y * BM;
    const int bn0 = blockIdx.x * BN;
    const int KT  = K / BK;

    float acc[2][NT][4];
    #pragma unroll
    for (int a=0;a<2;a++)
        #pragma unroll
        for (int b=0;b<NT;b++)
            #pragma unroll
            for (int c=0;c<4;c++) acc[a][b][c]=0.f;

    auto issue = [&](int kt, int s){
        const float* ag = A + (size_t)bm0 * K + (size_t)kt * BK;
        #pragma unroll
        for (int r=0;r<2;r++){
            int q = tid + r*256;            // 512 chunks of 16B
            int row = q >> 2, cc = (q & 3) * 4;
            cp16(smem_u32(&As[s][row*AST + cc]), ag + (size_t)row*K + cc);
        }
        const float* bg = B + (size_t)kt * BK * N + bn0;
        constexpr int BCH = BN/64;          // 16B chunks per thread
        #pragma unroll
        for (int r=0;r<BCH;r++){
            int q = tid + r*256;
            int row = q / (BN/4), cc = (q % (BN/4)) * 4;
            cp16(smem_u32(&Bs[s][row*BST + cc]), bg + (size_t)row*N + cc);
        }
    };

    issue(0, 0);
    cp_commit();

    for (int kt=0; kt<KT; kt++){
        cp_wait<0>();
        __syncthreads();
        const int s = kt & 1;
        if (kt+1 < KT) issue(kt+1, s^1);
        cp_commit();
        const float* as = As[s];
        const float* bs = Bs[s];
        #pragma unroll
        for (int k8=0; k8<2; k8++){
            uint32_t ah[2][4], al[2][4], bh[NT][2], bl[NT][2];
            #pragma unroll
            for (int mt=0; mt<2; mt++){
                const float* ap = as + (wm*32 + mt*16 + grp)*AST + k8*8 + qd;
                split_tf32(ap[0],        ah[mt][0], al[mt][0]);  // (grp,   qd)
                split_tf32(ap[8*AST],    ah[mt][1], al[mt][1]);  // (grp+8, qd)
                split_tf32(ap[4],        ah[mt][2], al[mt][2]);  // (grp,   qd+4)
                split_tf32(ap[8*AST+4],  ah[mt][3], al[mt][3]);  // (grp+8, qd+4)
            }
            #pragma unroll
            for (int nt=0; nt<NT; nt++){
                const float* bp = bs + (k8*8 + qd)*BST + wn*WN + nt*8 + grp;
                split_tf32(bp[0],        bh[nt][0], bl[nt][0]);  // (qd,   n)
                split_tf32(bp[4*BST],    bh[nt][1], bl[nt][1]);  // (qd+4, n)
            }
            #pragma unroll
            for (int mt=0; mt<2; mt++)
                #pragma unroll
                for (int nt=0; nt<NT; nt++){
                    mma_tf32(acc[mt][nt], al[mt], bh[nt]);   // lo*hi
                    mma_tf32(acc[mt][nt], ah[mt], bl[nt]);   // hi*lo
                    mma_tf32(acc[mt][nt], ah[mt], bh[nt]);   // hi*hi last (largest)
                }
        }
    }

    // epilogue
    #pragma unroll
    for (int mt=0; mt<2; mt++){
        #pragma unroll
        for (int nt=0; nt<NT; nt++){
            int row = bm0 + wm*32 + mt*16 + grp;
            int col = bn0 + wn*WN + nt*8 + qd*2;
            float w0a = 0.f, w0b = 0.f;
            if (EPI == 3){ w0a = w0[col]; w0b = w0[col+1]; }
            float v0 = epi_f<EPI>(acc[mt][nt][0], w0a);
            float v1 = epi_f<EPI>(acc[mt][nt][1], w0b);
            float v2 = epi_f<EPI>(acc[mt][nt][2], w0a);
            float v3 = epi_f<EPI>(acc[mt][nt][3], w0b);
            *(float2*)(C + (size_t)row*N + col)     = make_float2(v0, v1);
            *(float2*)(C + (size_t)(row+8)*N + col) = make_float2(v2, v3);
        }
    }
}

// ---------------- WKV sequential scan --------------------------------------
// grid 128 blocks: blockIdx = bh*4 + colgroup; 128 threads: j = tid&15 (col),
// g = tid>>4 (row group of 8). State S[8] (rows g*8..g*8+7, column cg*16+j)
// lives in registers. r/k/v/w streamed via cp.async ring of 8 slots, depth 4.
__global__ __launch_bounds__(128) void wkv_scan(
    const float* __restrict__ R, const float* __restrict__ Kk,
    const float* __restrict__ V, const float* __restrict__ W,
    const float* __restrict__ U, float* __restrict__ Y)
{
    const int bid = blockIdx.x;
    const int bh = bid >> 2, cg = bid & 3;
    const int b = bh >> 4, h = bh & 15;
    const int tid = threadIdx.x;
    const int j = tid & 15, g = tid >> 4;      // g in [0,8)
    const int col = cg*16 + j;

    __shared__ __align__(16) float sv[8][4][HDIM];  // ring: [slot][r,k,v,w][64]
    __shared__ float sp[2][8][16];

    float S[8], uu[8];
    #pragma unroll
    for (int ii=0; ii<8; ii++){ S[ii]=0.f; uu[ii]=U[h*HDIM + g*8 + ii]; }

    // this thread fills two of the 256 values per step
    const int q0 = tid, q1 = tid + 128;
    const int v0 = q0 >> 6, i0 = q0 & 63;
    const int v1 = q1 >> 6, i1 = q1 & 63;
    const float* p0 = (v0==0?R:Kk) + (size_t)b*Tt*Dd + h*HDIM + i0;
    const float* p1 = (v1==2?V:W)  + (size_t)b*Tt*Dd + h*HDIM + i1;

    auto issue = [&](int t){
        int s = t & 7;
        int tc = (t < Tt) ? t : (Tt-1);
        cp4(smem_u32(&sv[s][v0][i0]), p0 + (size_t)tc*Dd);
        cp4(smem_u32(&sv[s][v1][i1]), p1 + (size_t)tc*Dd);
        cp_commit();
    };

    for (int t=0; t<4; t++) issue(t);
    cp_wait<3>();
    __syncthreads();

    float* yout = Y + (size_t)b*Tt*Dd + h*HDIM + col;

    for (int t=0; t<Tt; t++){
        const int s = t & 7;
        float vj = sv[s][2][col];
        float rr[8], kk[8], ww[8];
        {
            const float4* r4 = (const float4*)&sv[s][0][g*8];
            const float4* k4 = (const float4*)&sv[s][1][g*8];
            const float4* w4 = (const float4*)&sv[s][3][g*8];
            float4 a;
            a = r4[0]; rr[0]=a.x; rr[1]=a.y; rr[2]=a.z; rr[3]=a.w;
            a = r4[1]; rr[4]=a.x; rr[5]=a.y; rr[6]=a.z; rr[7]=a.w;
            a = k4[0]; kk[0]=a.x; kk[1]=a.y; kk[2]=a.z; kk[3]=a.w;
            a = k4[1]; kk[4]=a.x; kk[5]=a.y; kk[6]=a.z; kk[7]=a.w;
            a = w4[0]; ww[0]=a.x; ww[1]=a.y; ww[2]=a.z; ww[3]=a.w;
            a = w4[1]; ww[4]=a.x; ww[5]=a.y; ww[6]=a.z; ww[7]=a.w;
        }
        float acc = 0.f;
        #pragma unroll
        for (int ii=0; ii<8; ii++){
            float kv = kk[ii] * vj;
            acc += rr[ii] * fmaf(uu[ii], kv, S[ii]);  // y uses S before update
            S[ii] = fmaf(ww[ii], S[ii], kv);
        }
        sp[t&1][g][j] = acc;
        issue(t+4);
        cp_wait<3>();      // slot (t+1) ready (mine); bar publishes everyone's
        __syncthreads();
        if (g == 0){
            float y = 0.f;
            #pragma unroll
            for (int gg=0; gg<8; gg++) y += sp[t&1][gg][j];
            yout[(size_t)t*Dd] = y;
        }
    }
}

// ---------------- per-head GroupNorm + silu-gate ----------------------------
__global__ __launch_bounds__(256) void gn_gate(
    const float* __restrict__ Yv, const float* __restrict__ G,
    const float* __restrict__ gamma, const float* __restrict__ beta,
    float* __restrict__ out)
{
    int warp = threadIdx.x >> 5, lane = threadIdx.x & 31;
    int grpi = blockIdx.x * 8 + warp;         // B*T*H = 65536 groups
    size_t base = (size_t)grpi * HDIM;
    float a  = Yv[base + lane];
    float b2 = Yv[base + lane + 32];
    float s  = a + b2, ss = a*a + b2*b2;
    #pragma unroll
    for (int o=16; o>0; o>>=1){
        s  += __shfl_xor_sync(0xffffffffu, s,  o);
        ss += __shfl_xor_sync(0xffffffffu, ss, o);
    }
    float mean = s * (1.f/HDIM);
    float var  = ss * (1.f/HDIM) - mean*mean;
    float inv  = rsqrtf(var + 1e-5f);
    int h = grpi & (Hh-1);
    int d0 = h*HDIM + lane;
    float o0 = (a  - mean)*inv*gamma[d0]      + beta[d0];
    float o1 = (b2 - mean)*inv*gamma[d0+32]   + beta[d0+32];
    out[base + lane]      = o0 * G[base + lane];
    out[base + lane + 32] = o1 * G[base + lane + 32];
}

// ---------------- launch ----------------------------------------------------
extern "C" void kernel_launch(void* const* d_in, const int* in_sizes, int n_in,
                              void* d_out, int out_size)
{
    const float* x     = (const float*)d_in[0];
    const float* mu_w  = (const float*)d_in[1];
    const float* mu_r  = (const float*)d_in[2];
    const float* mu_k  = (const float*)d_in[3];
    const float* mu_v  = (const float*)d_in[4];
    const float* mu_g  = (const float*)d_in[5];
    const float* w0    = (const float*)d_in[6];
    const float* Aw    = (const float*)d_in[7];
    const float* Bw    = (const float*)d_in[8];
    const float* Wr    = (const float*)d_in[9];
    const float* Wk    = (const float*)d_in[10];
    const float* Wv    = (const float*)d_in[11];
    const float* Wg    = (const float*)d_in[12];
    const float* Wo    = (const float*)d_in[13];
    const float* u     = (const float*)d_in[14];
    const float* gamma = (const float*)d_in[15];
    const float* beta  = (const float*)d_in[16];
    float* out = (float*)d_out;

    float *xw,*xr,*xk,*xv,*xg,*pr,*pk,*pv,*pg,*pw,*ph,*py,*pyg;
    cudaGetSymbolAddress((void**)&xw,  g_xw);
    cudaGetSymbolAddress((void**)&xr,  g_xr);
    cudaGetSymbolAddress((void**)&xk,  g_xk);
    cudaGetSymbolAddress((void**)&xv,  g_xv);
    cudaGetSymbolAddress((void**)&xg,  g_xg);
    cudaGetSymbolAddress((void**)&pr,  g_r);
    cudaGetSymbolAddress((void**)&pk,  g_k);
    cudaGetSymbolAddress((void**)&pv,  g_v);
    cudaGetSymbolAddress((void**)&pg,  g_g);
    cudaGetSymbolAddress((void**)&pw,  g_w);
    cudaGetSymbolAddress((void**)&ph,  g_h);
    cudaGetSymbolAddress((void**)&py,  g_y);
    cudaGetSymbolAddress((void**)&pyg, g_yg);

    // 1) token-shift interpolations
    prep_kernel<<<(Bb*Tt*Dd/4 + 255)/256, 256>>>(x, mu_w, mu_r, mu_k, mu_v, mu_g);

    // 2) LoRA decay path: tanh(xw @ Aw) @ Bw -> wdec = exp(-exp(w0 + .))
    gemm_tf32<64, 2><<<dim3(1, MM/128), 256>>>(xw, Aw, ph, MM, 64, Dd, nullptr);
    gemm_tf32<128,3><<<dim3(Dd/128, MM/128), 256>>>(ph, Bw, pw, MM, Dd, 64, w0);

    // 3) projections
    gemm_tf32<128,0><<<dim3(Dd/128, MM/128), 256>>>(xr, Wr, pr, MM, Dd, Dd, nullptr);
    gemm_tf32<128,0><<<dim3(Dd/128, MM/128), 256>>>(xk, Wk, pk, MM, Dd, Dd, nullptr);
    gemm_tf32<128,0><<<dim3(Dd/128, MM/128), 256>>>(xv, Wv, pv, MM, Dd, Dd, nullptr);
    gemm_tf32<128,1><<<dim3(Dd/128, MM/128), 256>>>(xg, Wg, pg, MM, Dd, Dd, nullptr);

    // 4) sequential WKV scan
    wkv_scan<<<128, 128>>>(pr, pk, pv, pw, u, py);

    // 5) per-head GroupNorm + silu gate
    gn_gate<<<(Bb*Tt*Hh)/8, 256>>>(py, pg, gamma, beta, pyg);

    // 6) output projection
    gemm_tf32<128,0><<<dim3(Dd/128, MM/128), 256>>>(pyg, Wo, out, MM, Dd, Dd, nullptr);
}